// round 13
// baseline (speedup 1.0000x reference)
#include <cuda_runtime.h>
#include <cstdint>
#include <math.h>

#define HID 64
#define CIN 4
#define HH 8
#define WW 8
#define NB 32

// Repacked masked weights (persistent device scratch; no allocation).
// g_w0p: [s][pos(4 maskA)][ic(4)][oc(64)]
// g_w12p: float4 units, unit index (((layer*2+s)*5+pos)*16+icg)*64+oc, holding ic=icg*4..+3
__device__ float  g_w0p[2 * 4 * 4 * 64];
__device__ float4 g_w12p[2 * 2 * 5 * 16 * 64];

__global__ void prep_kernel(const float* __restrict__ mu_w0, const float* __restrict__ mu_w1,
                            const float* __restrict__ mu_w2,
                            const float* __restrict__ lv_w0, const float* __restrict__ lv_w1,
                            const float* __restrict__ lv_w2) {
    int idx = blockIdx.x * blockDim.x + threadIdx.x;
    const int kyB[5] = {0, 0, 0, 1, 1};
    const int kxB[5] = {0, 1, 2, 0, 1};
    if (idx < 2048) {
        int oc = idx & 63; int ic = (idx >> 6) & 3; int pos = (idx >> 8) & 3; int s = idx >> 10;
        const float* w = s ? lv_w0 : mu_w0;
        g_w0p[idx] = w[((oc * CIN + ic) * 3 + kyB[pos]) * 3 + kxB[pos]];
    }
    int j = idx - 2048;
    if (j >= 0 && j < 2 * 2 * 5 * 16 * 64 * 4) {
        int t = j;
        int e   = t & 3;  t >>= 2;
        int oc  = t & 63; t >>= 6;
        int icg = t & 15; t >>= 4;
        int pos = t % 5;  t /= 5;
        int s   = t & 1;  t >>= 1;
        int layer = t;
        int ic = icg * 4 + e;
        const float* w = layer ? (s ? lv_w2 : mu_w2) : (s ? lv_w1 : mu_w1);
        ((float*)g_w12p)[j] = w[((oc * HID + ic) * 3 + kyB[pos]) * 3 + kxB[pos]];
    }
}

__device__ __forceinline__ float eluf(float v) { return v > 0.f ? v : expm1f(v); }

__device__ __forceinline__ uint32_t smem_u32(const void* p) {
    uint32_t a;
    asm("{ .reg .u64 t; cvta.to.shared.u64 t, %1; cvt.u32.u64 %0, t; }" : "=r"(a) : "l"(p));
    return a;
}
__device__ __forceinline__ void st_cluster_f32(uint32_t addr, float v) {
    asm volatile("st.shared::cluster.f32 [%0], %1;" :: "r"(addr), "f"(v) : "memory");
}

// packed f32x2 fma: acc(lo,hi) += a(lo,hi) * b(lo,hi)
__device__ __forceinline__ void fma2(unsigned long long& acc,
                                     unsigned long long a, unsigned long long b) {
    asm("fma.rn.f32x2 %0, %1, %2, %0;" : "+l"(acc) : "l"(a), "l"(b));
}
__device__ __forceinline__ float hsum2(unsigned long long a, unsigned long long b) {
    float2 fa = *reinterpret_cast<float2*>(&a);
    float2 fb = *reinterpret_cast<float2*>(&b);
    return (fa.x + fa.y) + (fb.x + fb.y);
}

__device__ __forceinline__ void mbar_init(uint32_t a, uint32_t cnt) {
    asm volatile("mbarrier.init.shared.b64 [%0], %1;" :: "r"(a), "r"(cnt) : "memory");
}
__device__ __forceinline__ void mbar_arrive_local(uint32_t a) {
    asm volatile("mbarrier.arrive.release.cluster.shared::cta.b64 _, [%0];"
                 :: "r"(a) : "memory");
}
__device__ __forceinline__ void mbar_arrive_remote(uint32_t a) {
    asm volatile("mbarrier.arrive.release.cluster.shared::cluster.b64 _, [%0];"
                 :: "r"(a) : "memory");
}
__device__ __forceinline__ void mbar_wait(uint32_t a, uint32_t parity) {
    asm volatile(
        "{\n\t.reg .pred P;\n\t"
        "WL_%=:\n\t"
        "mbarrier.try_wait.parity.acquire.cluster.shared::cta.b64 P, [%0], %1, 0x989680;\n\t"
        "@P bra.uni WD_%=;\n\t"
        "bra.uni WL_%=;\n\t"
        "WD_%=:\n\t}"
        :: "r"(a), "r"(parity) : "memory");
}

// ---- dynamic smem float offsets ----
#define OFF_W12   0        // 40960 floats (layer-1/2 weights for this stack, float4 view)
#define OFF_SH0   40960    // 9*10*64 padded h0
#define OFF_SH1   46720    // 9*10*64 padded h1
#define OFF_SW0   52480    // 4*4*64
#define OFF_SWO   53504    // 4*64
#define OFF_SB0   53760
#define OFF_SB1   53824
#define OFF_SB2   53888
#define OFF_SBO   53952    // 16
#define OFF_SY    53968    // 4*9*10 = 360 (pad 368)
#define OFF_SX    54336    // 256
#define OFF_SH2   54592    // 4*64
#define OFF_SPART 54848    // 8*4*64
#define OFF_SXCHG 56896    // [stack][buf][q][ch] = 64
#define OFF_SSUM  56960    // 16
#define OFF_MBAR  56976    // 2 mbarriers (8B each), 8B-aligned
#define SMEM_FLOATS 56980
#define SMEM_BYTES (SMEM_FLOATS * 4)

__global__ void __launch_bounds__(512, 1) __cluster_dims__(2, 1, 1)
made_wave_kernel(const float* __restrict__ x,
                 const float* __restrict__ mu_b0, const float* __restrict__ mu_b1,
                 const float* __restrict__ mu_b2, const float* __restrict__ mu_wo,
                 const float* __restrict__ mu_bo,
                 const float* __restrict__ lv_b0, const float* __restrict__ lv_b1,
                 const float* __restrict__ lv_b2, const float* __restrict__ lv_wo,
                 const float* __restrict__ lv_bo,
                 float* __restrict__ out)
{
    extern __shared__ float sm[];
    const int tid = threadIdx.x;
    const int rank = blockIdx.x & 1;      // 0 = mu stack, 1 = lv stack
    const int b = blockIdx.x >> 1;

    // ---- stage weights/biases/x, zero activation buffers ----
    {
        float4* w12 = (float4*)(sm + OFF_W12);
        #pragma unroll
        for (int l = 0; l < 2; l++) {
            const float4* src = g_w12p + (l * 2 + rank) * 5120;
            float4* dst = w12 + l * 5120;
            for (int i = tid; i < 5120; i += 512) dst[i] = src[i];
        }
        for (int i = tid; i < 1024; i += 512) sm[OFF_SW0 + i] = g_w0p[rank * 1024 + i];
        const float* wo = rank ? lv_wo : mu_wo;
        const float* b0 = rank ? lv_b0 : mu_b0;
        const float* b1 = rank ? lv_b1 : mu_b1;
        const float* b2 = rank ? lv_b2 : mu_b2;
        const float* bo = rank ? lv_bo : mu_bo;
        if (tid < 256) sm[OFF_SWO + tid] = wo[tid];
        if (tid < 64) {
            sm[OFF_SB0 + tid] = b0[tid];
            sm[OFF_SB1 + tid] = b1[tid];
            sm[OFF_SB2 + tid] = b2[tid];
        }
        if (tid < 4) sm[OFF_SBO + tid] = bo[tid];
        if (tid < 256) sm[OFF_SX + tid] = x[b * 256 + tid];
        for (int i = tid; i < 5760; i += 512) { sm[OFF_SH0 + i] = 0.f; sm[OFF_SH1 + i] = 0.f; }
        for (int i = tid; i < 360; i += 512) sm[OFF_SY + i] = 0.f;
        if (tid == 0) {
            uint32_t mb = smem_u32(sm + OFF_MBAR);
            mbar_init(mb, 32);
            mbar_init(mb + 8, 32);
        }
    }
    __syncthreads();
    // mbarrier init on both CTAs must be visible before any remote arrive.
    asm volatile("barrier.cluster.arrive.aligned;" ::: "memory");
    asm volatile("barrier.cluster.wait.aligned;" ::: "memory");

    // remote addresses of peer's sxchg + mbarriers
    uint32_t lsx = smem_u32(sm + OFF_SXCHG);
    uint32_t lmb = smem_u32(sm + OFF_MBAR);
    uint32_t rsx, rmb;
    asm("mapa.shared::cluster.u32 %0, %1, %2;" : "=r"(rsx) : "r"(lsx), "r"(rank ^ 1));
    asm("mapa.shared::cluster.u32 %0, %1, %2;" : "=r"(rmb) : "r"(lmb), "r"(rank ^ 1));

    const float4* w1 = (const float4*)(sm + OFF_W12);
    const float4* w2 = w1 + 5120;

    float lsum = 0.f;

    for (int t = 0; t < 22; t++) {
        const int th = t >> 1, par = t & 1;
        // quadrant q: pixel (rq = th - q, cq = par + 2q); active iff 0 <= rq < 8
        int rq0 = th,     rq1 = th - 1, rq2 = th - 2, rq3 = th - 3;
        int re0 = ((unsigned)rq0 < 8u) ? rq0 : 0;
        int re1 = ((unsigned)rq1 < 8u) ? rq1 : 0;
        int re2 = ((unsigned)rq2 < 8u) ? rq2 : 0;
        int re3 = ((unsigned)rq3 < 8u) ? rq3 : 0;
        // padded-cell float offsets of the 4 pixel centers (in [row][col][64] layout)
        const int hb0 = ((re0 + 1) * 10 + (par + 1)) * 64;
        const int hb1 = ((re1 + 1) * 10 + (par + 3)) * 64;
        const int hb2 = ((re2 + 1) * 10 + (par + 5)) * 64;
        const int hb3 = ((re3 + 1) * 10 + (par + 7)) * 64;

        // ---- Phase A: h0 = elu(maskA conv over padded y) ----
        if (tid < 256) {
            int q = tid >> 6, oc = tid & 63;
            int rq = th - q, cq = par + 2 * q;
            if ((unsigned)rq < 8u) {
                float acc = sm[OFF_SB0 + oc];
                int yb = (rq + 1) * 10 + (cq + 1);
                #pragma unroll
                for (int ic = 0; ic < 4; ic++) {
                    const float* yp = sm + OFF_SY + ic * 90 + yb;
                    acc += sm[OFF_SW0 + (0 * 4 + ic) * 64 + oc] * yp[-11];
                    acc += sm[OFF_SW0 + (1 * 4 + ic) * 64 + oc] * yp[-10];
                    acc += sm[OFF_SW0 + (2 * 4 + ic) * 64 + oc] * yp[-9];
                    acc += sm[OFF_SW0 + (3 * 4 + ic) * 64 + oc] * yp[-1];
                }
                sm[OFF_SH0 + ((rq + 1) * 10 + (cq + 1)) * 64 + oc] = eluf(acc);
            }
        }
        __syncthreads();

        // maskB neighbor float offsets: (-1,-1),(-1,0),(-1,1),(0,-1),(0,0)
        const int OFS0 = -704, OFS1 = -640, OFS2 = -576, OFS3 = -64, OFS4 = 0;

        // ---- Phase B: layer-1 conv (f32x2, weights reused across 4 pixels) ----
        {
            int oc = tid & 63, sub = tid >> 6;
            int icg0 = sub * 2;
            unsigned long long a0l=0,a0h=0,a1l=0,a1h=0,a2l=0,a2h=0,a3l=0,a3h=0;
            #pragma unroll
            for (int pos = 0; pos < 5; pos++) {
                const int o = (pos == 0) ? OFS0 : (pos == 1) ? OFS1 : (pos == 2) ? OFS2
                              : (pos == 3) ? OFS3 : OFS4;
                const ulonglong2* p0 = (const ulonglong2*)(sm + OFF_SH0 + hb0 + o);
                const ulonglong2* p1 = (const ulonglong2*)(sm + OFF_SH0 + hb1 + o);
                const ulonglong2* p2 = (const ulonglong2*)(sm + OFF_SH0 + hb2 + o);
                const ulonglong2* p3 = (const ulonglong2*)(sm + OFF_SH0 + hb3 + o);
                #pragma unroll
                for (int kk = 0; kk < 2; kk++) {
                    ulonglong2 wv = *(const ulonglong2*)(w1 + (pos * 16 + icg0 + kk) * 64 + oc);
                    ulonglong2 h;
                    h = p0[icg0 + kk]; fma2(a0l, wv.x, h.x); fma2(a0h, wv.y, h.y);
                    h = p1[icg0 + kk]; fma2(a1l, wv.x, h.x); fma2(a1h, wv.y, h.y);
                    h = p2[icg0 + kk]; fma2(a2l, wv.x, h.x); fma2(a2h, wv.y, h.y);
                    h = p3[icg0 + kk]; fma2(a3l, wv.x, h.x); fma2(a3h, wv.y, h.y);
                }
            }
            sm[OFF_SPART + (sub * 4 + 0) * 64 + oc] = hsum2(a0l, a0h);
            sm[OFF_SPART + (sub * 4 + 1) * 64 + oc] = hsum2(a1l, a1h);
            sm[OFF_SPART + (sub * 4 + 2) * 64 + oc] = hsum2(a2l, a2h);
            sm[OFF_SPART + (sub * 4 + 3) * 64 + oc] = hsum2(a3l, a3h);
        }
        __syncthreads();
        if (tid < 256) {
            int q = tid >> 6, oc = tid & 63;
            int rq = th - q, cq = par + 2 * q;
            if ((unsigned)rq < 8u) {
                float v = sm[OFF_SB1 + oc];
                #pragma unroll
                for (int s = 0; s < 8; s++) v += sm[OFF_SPART + (s * 4 + q) * 64 + oc];
                sm[OFF_SH1 + ((rq + 1) * 10 + (cq + 1)) * 64 + oc] = eluf(v);
            }
        }
        __syncthreads();

        // ---- Phase C: layer-2 conv (f32x2) ----
        {
            int oc = tid & 63, sub = tid >> 6;
            int icg0 = sub * 2;
            unsigned long long a0l=0,a0h=0,a1l=0,a1h=0,a2l=0,a2h=0,a3l=0,a3h=0;
            #pragma unroll
            for (int pos = 0; pos < 5; pos++) {
                const int o = (pos == 0) ? OFS0 : (pos == 1) ? OFS1 : (pos == 2) ? OFS2
                              : (pos == 3) ? OFS3 : OFS4;
                const ulonglong2* p0 = (const ulonglong2*)(sm + OFF_SH1 + hb0 + o);
                const ulonglong2* p1 = (const ulonglong2*)(sm + OFF_SH1 + hb1 + o);
                const ulonglong2* p2 = (const ulonglong2*)(sm + OFF_SH1 + hb2 + o);
                const ulonglong2* p3 = (const ulonglong2*)(sm + OFF_SH1 + hb3 + o);
                #pragma unroll
                for (int kk = 0; kk < 2; kk++) {
                    ulonglong2 wv = *(const ulonglong2*)(w2 + (pos * 16 + icg0 + kk) * 64 + oc);
                    ulonglong2 h;
                    h = p0[icg0 + kk]; fma2(a0l, wv.x, h.x); fma2(a0h, wv.y, h.y);
                    h = p1[icg0 + kk]; fma2(a1l, wv.x, h.x); fma2(a1h, wv.y, h.y);
                    h = p2[icg0 + kk]; fma2(a2l, wv.x, h.x); fma2(a2h, wv.y, h.y);
                    h = p3[icg0 + kk]; fma2(a3l, wv.x, h.x); fma2(a3h, wv.y, h.y);
                }
            }
            sm[OFF_SPART + (sub * 4 + 0) * 64 + oc] = hsum2(a0l, a0h);
            sm[OFF_SPART + (sub * 4 + 1) * 64 + oc] = hsum2(a1l, a1h);
            sm[OFF_SPART + (sub * 4 + 2) * 64 + oc] = hsum2(a2l, a2h);
            sm[OFF_SPART + (sub * 4 + 3) * 64 + oc] = hsum2(a3l, a3h);
        }
        __syncthreads();
        if (tid < 256) {
            int q = tid >> 6, oc = tid & 63;
            int rq = th - q;
            if ((unsigned)rq < 8u) {
                float v = sm[OFF_SB2 + oc];
                #pragma unroll
                for (int s = 0; s < 8; s++) v += sm[OFF_SPART + (s * 4 + q) * 64 + oc];
                sm[OFF_SH2 + q * 64 + oc] = eluf(v);
            }
        }
        __syncthreads();

        // ---- Phase D: 1x1 output conv; writers publish via mbarrier (count=32) ----
        if (tid < 128) {
            int q = tid >> 5, lane = tid & 31, ch = lane >> 3, ss = lane & 7;
            float acc = 0.f;
            #pragma unroll
            for (int i = 0; i < 8; i++) {
                int ic = ss * 8 + i;
                acc += sm[OFF_SWO + ch * 64 + ic] * sm[OFF_SH2 + q * 64 + ic];
            }
            acc += __shfl_xor_sync(0xffffffffu, acc, 1);
            acc += __shfl_xor_sync(0xffffffffu, acc, 2);
            acc += __shfl_xor_sync(0xffffffffu, acc, 4);
            int rq = th - q;
            if (ss == 0) {
                if ((unsigned)rq < 8u) {
                    float v = acc + sm[OFF_SBO + ch];
                    int idx = rank * 32 + par * 16 + q * 4 + ch;
                    sm[OFF_SXCHG + idx] = v;
                    st_cluster_f32(rsx + idx * 4, v);
                }
                // arrive (release, cluster scope) on both CTAs' buffer barrier;
                // inactive writer slots still arrive to keep the count at 32.
                mbar_arrive_local(lmb + (par << 3));
                mbar_arrive_remote(rmb + (par << 3));
            }
        }

        // ---- y update: only the 16 updater threads wait on the mbarrier ----
        if (tid < 16) {
            mbar_wait(lmb + (par << 3), (t >> 1) & 1);
            int q = tid >> 2, ch = tid & 3;
            int rq = th - q, cq = par + 2 * q;
            if ((unsigned)rq < 8u) {
                float mu = sm[OFF_SXCHG + par * 16 + q * 4 + ch];
                float lv = sm[OFF_SXCHG + 32 + par * 16 + q * 4 + ch];
                float logstd = 0.5f * lv;
                float yv = __fdividef(sm[OFF_SX + (ch * 8 + rq) * 8 + cq] - mu,
                                      __expf(logstd) + 1e-12f);
                sm[OFF_SY + ch * 90 + (rq + 1) * 10 + (cq + 1)] = yv;
                if (rank == 0) out[((b * 4 + ch) * 8 + rq) * 8 + cq] = yv;
                lsum += logstd;
            }
        }
        __syncthreads();
    }

    if (tid < 16) sm[OFF_SSUM + tid] = lsum;
    __syncthreads();
    if (rank == 0 && tid == 0) {
        float s = 0.f;
        #pragma unroll
        for (int i = 0; i < 16; i++) s += sm[OFF_SSUM + i];
        out[NB * CIN * HH * WW + b] = s;
    }

    // keep both CTAs resident until all cross-CTA traffic has fully drained
    asm volatile("barrier.cluster.arrive.aligned;" ::: "memory");
    asm volatile("barrier.cluster.wait.aligned;" ::: "memory");
}

extern "C" void kernel_launch(void* const* d_in, const int* in_sizes, int n_in,
                              void* d_out, int out_size) {
    (void)in_sizes; (void)n_in; (void)out_size;
    const float* x     = (const float*)d_in[0];
    const float* mu_w0 = (const float*)d_in[1];
    const float* mu_b0 = (const float*)d_in[2];
    const float* mu_w1 = (const float*)d_in[3];
    const float* mu_b1 = (const float*)d_in[4];
    const float* mu_w2 = (const float*)d_in[5];
    const float* mu_b2 = (const float*)d_in[6];
    const float* mu_wo = (const float*)d_in[7];
    const float* mu_bo = (const float*)d_in[8];
    const float* lv_w0 = (const float*)d_in[9];
    const float* lv_b0 = (const float*)d_in[10];
    const float* lv_w1 = (const float*)d_in[11];
    const float* lv_b1 = (const float*)d_in[12];
    const float* lv_w2 = (const float*)d_in[13];
    const float* lv_b2 = (const float*)d_in[14];
    const float* lv_wo = (const float*)d_in[15];
    const float* lv_bo = (const float*)d_in[16];
    float* out = (float*)d_out;

    cudaFuncSetAttribute(made_wave_kernel,
                         cudaFuncAttributeMaxDynamicSharedMemorySize, SMEM_BYTES);

    int total = 2048 + 2 * 2 * 5 * 16 * 64 * 4;
    prep_kernel<<<(total + 255) / 256, 256>>>(mu_w0, mu_w1, mu_w2, lv_w0, lv_w1, lv_w2);
    made_wave_kernel<<<2 * NB, 512, SMEM_BYTES>>>(x, mu_b0, mu_b1, mu_b2, mu_wo, mu_bo,
                                                  lv_b0, lv_b1, lv_b2, lv_wo, lv_bo, out);
}

// round 14
// speedup vs baseline: 1.2245x; 1.2245x over previous
#include <cuda_runtime.h>
#include <cstdint>
#include <math.h>

#define HID 64
#define CIN 4
#define HH 8
#define WW 8
#define NB 32

// Repacked masked weights (persistent device scratch; no allocation).
// g_w0p: [s][pos(4 maskA)][ic(4)][oc(64)]
// g_w12p: float4 units, unit index (((layer*2+s)*5+pos)*16+icg)*64+oc, holding ic=icg*4..+3
__device__ float  g_w0p[2 * 4 * 4 * 64];
__device__ float4 g_w12p[2 * 2 * 5 * 16 * 64];

__global__ void prep_kernel(const float* __restrict__ mu_w0, const float* __restrict__ mu_w1,
                            const float* __restrict__ mu_w2,
                            const float* __restrict__ lv_w0, const float* __restrict__ lv_w1,
                            const float* __restrict__ lv_w2) {
    int idx = blockIdx.x * blockDim.x + threadIdx.x;
    const int kyB[5] = {0, 0, 0, 1, 1};
    const int kxB[5] = {0, 1, 2, 0, 1};
    if (idx < 2048) {
        int oc = idx & 63; int ic = (idx >> 6) & 3; int pos = (idx >> 8) & 3; int s = idx >> 10;
        const float* w = s ? lv_w0 : mu_w0;
        g_w0p[idx] = w[((oc * CIN + ic) * 3 + kyB[pos]) * 3 + kxB[pos]];
    }
    int j = idx - 2048;
    if (j >= 0 && j < 2 * 2 * 5 * 16 * 64 * 4) {
        int t = j;
        int e   = t & 3;  t >>= 2;
        int oc  = t & 63; t >>= 6;
        int icg = t & 15; t >>= 4;
        int pos = t % 5;  t /= 5;
        int s   = t & 1;  t >>= 1;
        int layer = t;
        int ic = icg * 4 + e;
        const float* w = layer ? (s ? lv_w2 : mu_w2) : (s ? lv_w1 : mu_w1);
        ((float*)g_w12p)[j] = w[((oc * HID + ic) * 3 + kyB[pos]) * 3 + kxB[pos]];
    }
}

__device__ __forceinline__ float eluf(float v) { return v > 0.f ? v : expm1f(v); }

__device__ __forceinline__ uint32_t smem_u32(const void* p) {
    uint32_t a;
    asm("{ .reg .u64 t; cvta.to.shared.u64 t, %1; cvt.u32.u64 %0, t; }" : "=r"(a) : "l"(p));
    return a;
}
__device__ __forceinline__ void st_cluster_f32(uint32_t addr, float v) {
    asm volatile("st.shared::cluster.f32 [%0], %1;" :: "r"(addr), "f"(v) : "memory");
}

// ---- dynamic smem float offsets (no weight staging; weights live in registers) ----
#define OFF_SH0   0        // 9*10*64 padded h0
#define OFF_SH1   5760     // 9*10*64 padded h1
#define OFF_SW0   11520    // 4*4*64
#define OFF_SWO   12544    // 4*64
#define OFF_SB0   12800
#define OFF_SB1   12864
#define OFF_SB2   12928
#define OFF_SBO   12992    // 16
#define OFF_SY    13008    // 4*9*10 = 360 (pad 368)
#define OFF_SX    13376    // 256
#define OFF_SH2   13632    // 4*64
#define OFF_SPART 13888    // 8*4*64
#define OFF_SXCHG 15936    // [stack][buf][q][ch] = 64
#define OFF_SSUM  16000    // 16
#define SMEM_FLOATS 16016
#define SMEM_BYTES (SMEM_FLOATS * 4)

__global__ void __launch_bounds__(512, 1) __cluster_dims__(2, 1, 1)
made_wave_kernel(const float* __restrict__ x,
                 const float* __restrict__ mu_b0, const float* __restrict__ mu_b1,
                 const float* __restrict__ mu_b2, const float* __restrict__ mu_wo,
                 const float* __restrict__ mu_bo,
                 const float* __restrict__ lv_b0, const float* __restrict__ lv_b1,
                 const float* __restrict__ lv_b2, const float* __restrict__ lv_wo,
                 const float* __restrict__ lv_bo,
                 float* __restrict__ out)
{
    extern __shared__ float sm[];
    const int tid = threadIdx.x;
    const int rank = blockIdx.x & 1;      // 0 = mu stack, 1 = lv stack
    const int b = blockIdx.x >> 1;

    const int ocB = tid & 63;
    const int sub = tid >> 6;            // 0..7 -> ic slice [sub*8, sub*8+8)
    const int icg0 = sub * 2;

    // ---- per-thread register weights for layer-1/2 convs (loaded ONCE) ----
    float4 w1r[10], w2r[10];
    {
        const float4* gw1 = g_w12p + (0 * 2 + rank) * 5120;
        const float4* gw2 = g_w12p + (1 * 2 + rank) * 5120;
        #pragma unroll
        for (int pos = 0; pos < 5; pos++) {
            #pragma unroll
            for (int kk = 0; kk < 2; kk++) {
                w1r[pos * 2 + kk] = gw1[(pos * 16 + icg0 + kk) * 64 + ocB];
                w2r[pos * 2 + kk] = gw2[(pos * 16 + icg0 + kk) * 64 + ocB];
            }
        }
    }

    // ---- stage small constants/biases/x, zero activation buffers ----
    {
        for (int i = tid; i < 1024; i += 512) sm[OFF_SW0 + i] = g_w0p[rank * 1024 + i];
        const float* wo = rank ? lv_wo : mu_wo;
        const float* b0 = rank ? lv_b0 : mu_b0;
        const float* b1 = rank ? lv_b1 : mu_b1;
        const float* b2 = rank ? lv_b2 : mu_b2;
        const float* bo = rank ? lv_bo : mu_bo;
        if (tid < 256) sm[OFF_SWO + tid] = wo[tid];
        if (tid < 64) {
            sm[OFF_SB0 + tid] = b0[tid];
            sm[OFF_SB1 + tid] = b1[tid];
            sm[OFF_SB2 + tid] = b2[tid];
        }
        if (tid < 4) sm[OFF_SBO + tid] = bo[tid];
        if (tid < 256) sm[OFF_SX + tid] = x[b * 256 + tid];
        for (int i = tid; i < 5760; i += 512) { sm[OFF_SH0 + i] = 0.f; sm[OFF_SH1 + i] = 0.f; }
        for (int i = tid; i < 360; i += 512) sm[OFF_SY + i] = 0.f;
    }
    __syncthreads();

    // remote address of peer's sxchg
    uint32_t lsx = smem_u32(sm + OFF_SXCHG);
    uint32_t rsx;
    asm("mapa.shared::cluster.u32 %0, %1, %2;" : "=r"(rsx) : "r"(lsx), "r"(rank ^ 1));

    float lsum = 0.f;

    for (int t = 0; t < 22; t++) {
        const int th = t >> 1, par = t & 1;
        // quadrant q: pixel (rq = th - q, cq = par + 2q); active iff 0 <= rq < 8
        int rq0 = th,     rq1 = th - 1, rq2 = th - 2, rq3 = th - 3;
        int re0 = ((unsigned)rq0 < 8u) ? rq0 : 0;
        int re1 = ((unsigned)rq1 < 8u) ? rq1 : 0;
        int re2 = ((unsigned)rq2 < 8u) ? rq2 : 0;
        int re3 = ((unsigned)rq3 < 8u) ? rq3 : 0;
        // padded-cell float offsets of the 4 pixel centers (in [row][col][64] layout)
        const int hb0 = ((re0 + 1) * 10 + (par + 1)) * 64;
        const int hb1 = ((re1 + 1) * 10 + (par + 3)) * 64;
        const int hb2 = ((re2 + 1) * 10 + (par + 5)) * 64;
        const int hb3 = ((re3 + 1) * 10 + (par + 7)) * 64;

        // ---- Phase A: h0 = elu(maskA conv over padded y) ----
        if (tid < 256) {
            int q = tid >> 6, oc = tid & 63;
            int rq = th - q, cq = par + 2 * q;
            if ((unsigned)rq < 8u) {
                float acc = sm[OFF_SB0 + oc];
                int yb = (rq + 1) * 10 + (cq + 1);
                #pragma unroll
                for (int ic = 0; ic < 4; ic++) {
                    const float* yp = sm + OFF_SY + ic * 90 + yb;
                    acc += sm[OFF_SW0 + (0 * 4 + ic) * 64 + oc] * yp[-11];
                    acc += sm[OFF_SW0 + (1 * 4 + ic) * 64 + oc] * yp[-10];
                    acc += sm[OFF_SW0 + (2 * 4 + ic) * 64 + oc] * yp[-9];
                    acc += sm[OFF_SW0 + (3 * 4 + ic) * 64 + oc] * yp[-1];
                }
                sm[OFF_SH0 + ((rq + 1) * 10 + (cq + 1)) * 64 + oc] = eluf(acc);
            }
        }
        __syncthreads();

        // maskB neighbor float offsets: (-1,-1),(-1,0),(-1,1),(0,-1),(0,0)
        const int OFS0 = -704, OFS1 = -640, OFS2 = -576, OFS3 = -64, OFS4 = 0;

        // ---- Phase B: layer-1 conv (register weights, reused across 4 pixels) ----
        {
            float ac0 = 0.f, ac1 = 0.f, ac2 = 0.f, ac3 = 0.f;
            #pragma unroll
            for (int pos = 0; pos < 5; pos++) {
                const int o = (pos == 0) ? OFS0 : (pos == 1) ? OFS1 : (pos == 2) ? OFS2
                              : (pos == 3) ? OFS3 : OFS4;
                const float4* p0 = (const float4*)(sm + OFF_SH0 + hb0 + o);
                const float4* p1 = (const float4*)(sm + OFF_SH0 + hb1 + o);
                const float4* p2 = (const float4*)(sm + OFF_SH0 + hb2 + o);
                const float4* p3 = (const float4*)(sm + OFF_SH0 + hb3 + o);
                #pragma unroll
                for (int kk = 0; kk < 2; kk++) {
                    float4 wv = w1r[pos * 2 + kk];
                    float4 h;
                    h = p0[icg0 + kk]; ac0 += wv.x*h.x + wv.y*h.y + wv.z*h.z + wv.w*h.w;
                    h = p1[icg0 + kk]; ac1 += wv.x*h.x + wv.y*h.y + wv.z*h.z + wv.w*h.w;
                    h = p2[icg0 + kk]; ac2 += wv.x*h.x + wv.y*h.y + wv.z*h.z + wv.w*h.w;
                    h = p3[icg0 + kk]; ac3 += wv.x*h.x + wv.y*h.y + wv.z*h.z + wv.w*h.w;
                }
            }
            sm[OFF_SPART + (sub * 4 + 0) * 64 + ocB] = ac0;
            sm[OFF_SPART + (sub * 4 + 1) * 64 + ocB] = ac1;
            sm[OFF_SPART + (sub * 4 + 2) * 64 + ocB] = ac2;
            sm[OFF_SPART + (sub * 4 + 3) * 64 + ocB] = ac3;
        }
        __syncthreads();
        if (tid < 256) {
            int q = tid >> 6, oc = tid & 63;
            int rq = th - q, cq = par + 2 * q;
            if ((unsigned)rq < 8u) {
                float v = sm[OFF_SB1 + oc];
                #pragma unroll
                for (int s = 0; s < 8; s++) v += sm[OFF_SPART + (s * 4 + q) * 64 + oc];
                sm[OFF_SH1 + ((rq + 1) * 10 + (cq + 1)) * 64 + oc] = eluf(v);
            }
        }
        __syncthreads();

        // ---- Phase C: layer-2 conv (register weights) ----
        {
            float ac0 = 0.f, ac1 = 0.f, ac2 = 0.f, ac3 = 0.f;
            #pragma unroll
            for (int pos = 0; pos < 5; pos++) {
                const int o = (pos == 0) ? OFS0 : (pos == 1) ? OFS1 : (pos == 2) ? OFS2
                              : (pos == 3) ? OFS3 : OFS4;
                const float4* p0 = (const float4*)(sm + OFF_SH1 + hb0 + o);
                const float4* p1 = (const float4*)(sm + OFF_SH1 + hb1 + o);
                const float4* p2 = (const float4*)(sm + OFF_SH1 + hb2 + o);
                const float4* p3 = (const float4*)(sm + OFF_SH1 + hb3 + o);
                #pragma unroll
                for (int kk = 0; kk < 2; kk++) {
                    float4 wv = w2r[pos * 2 + kk];
                    float4 h;
                    h = p0[icg0 + kk]; ac0 += wv.x*h.x + wv.y*h.y + wv.z*h.z + wv.w*h.w;
                    h = p1[icg0 + kk]; ac1 += wv.x*h.x + wv.y*h.y + wv.z*h.z + wv.w*h.w;
                    h = p2[icg0 + kk]; ac2 += wv.x*h.x + wv.y*h.y + wv.z*h.z + wv.w*h.w;
                    h = p3[icg0 + kk]; ac3 += wv.x*h.x + wv.y*h.y + wv.z*h.z + wv.w*h.w;
                }
            }
            sm[OFF_SPART + (sub * 4 + 0) * 64 + ocB] = ac0;
            sm[OFF_SPART + (sub * 4 + 1) * 64 + ocB] = ac1;
            sm[OFF_SPART + (sub * 4 + 2) * 64 + ocB] = ac2;
            sm[OFF_SPART + (sub * 4 + 3) * 64 + ocB] = ac3;
        }
        __syncthreads();
        if (tid < 256) {
            int q = tid >> 6, oc = tid & 63;
            int rq = th - q;
            if ((unsigned)rq < 8u) {
                float v = sm[OFF_SB2 + oc];
                #pragma unroll
                for (int s = 0; s < 8; s++) v += sm[OFF_SPART + (s * 4 + q) * 64 + oc];
                sm[OFF_SH2 + q * 64 + oc] = eluf(v);
            }
        }
        __syncthreads();

        // ---- Phase D: 1x1 output conv, write result to own + peer sxchg ----
        if (tid < 128) {
            int q = tid >> 5, lane = tid & 31, ch = lane >> 3, ss = lane & 7;
            float acc = 0.f;
            #pragma unroll
            for (int i = 0; i < 8; i++) {
                int ic = ss * 8 + i;
                acc += sm[OFF_SWO + ch * 64 + ic] * sm[OFF_SH2 + q * 64 + ic];
            }
            acc += __shfl_xor_sync(0xffffffffu, acc, 1);
            acc += __shfl_xor_sync(0xffffffffu, acc, 2);
            acc += __shfl_xor_sync(0xffffffffu, acc, 4);
            int rq = th - q;
            if (ss == 0 && (unsigned)rq < 8u) {
                float v = acc + sm[OFF_SBO + ch];
                int idx = rank * 32 + par * 16 + q * 4 + ch;
                sm[OFF_SXCHG + idx] = v;
                st_cluster_f32(rsx + idx * 4, v);
            }
        }

        // cluster barrier: publishes remote sxchg stores (release/acquire) and
        // doubles as the CTA-wide barrier for this step's exchange.
        asm volatile("barrier.cluster.arrive.aligned;" ::: "memory");
        asm volatile("barrier.cluster.wait.aligned;" ::: "memory");

        // ---- y update (both CTAs compute y locally; rank 0 writes gmem) ----
        if (tid < 16) {
            int q = tid >> 2, ch = tid & 3;
            int rq = th - q, cq = par + 2 * q;
            if ((unsigned)rq < 8u) {
                float mu = sm[OFF_SXCHG + par * 16 + q * 4 + ch];
                float lv = sm[OFF_SXCHG + 32 + par * 16 + q * 4 + ch];
                float logstd = 0.5f * lv;
                float yv = __fdividef(sm[OFF_SX + (ch * 8 + rq) * 8 + cq] - mu,
                                      __expf(logstd) + 1e-12f);
                sm[OFF_SY + ch * 90 + (rq + 1) * 10 + (cq + 1)] = yv;
                if (rank == 0) out[((b * 4 + ch) * 8 + rq) * 8 + cq] = yv;
                lsum += logstd;
            }
        }
        __syncthreads();
    }

    if (tid < 16) sm[OFF_SSUM + tid] = lsum;
    __syncthreads();
    if (rank == 0 && tid == 0) {
        float s = 0.f;
        #pragma unroll
        for (int i = 0; i < 16; i++) s += sm[OFF_SSUM + i];
        out[NB * CIN * HH * WW + b] = s;
    }
}

extern "C" void kernel_launch(void* const* d_in, const int* in_sizes, int n_in,
                              void* d_out, int out_size) {
    (void)in_sizes; (void)n_in; (void)out_size;
    const float* x     = (const float*)d_in[0];
    const float* mu_w0 = (const float*)d_in[1];
    const float* mu_b0 = (const float*)d_in[2];
    const float* mu_w1 = (const float*)d_in[3];
    const float* mu_b1 = (const float*)d_in[4];
    const float* mu_w2 = (const float*)d_in[5];
    const float* mu_b2 = (const float*)d_in[6];
    const float* mu_wo = (const float*)d_in[7];
    const float* mu_bo = (const float*)d_in[8];
    const float* lv_w0 = (const float*)d_in[9];
    const float* lv_b0 = (const float*)d_in[10];
    const float* lv_w1 = (const float*)d_in[11];
    const float* lv_b1 = (const float*)d_in[12];
    const float* lv_w2 = (const float*)d_in[13];
    const float* lv_b2 = (const float*)d_in[14];
    const float* lv_wo = (const float*)d_in[15];
    const float* lv_bo = (const float*)d_in[16];
    float* out = (float*)d_out;

    cudaFuncSetAttribute(made_wave_kernel,
                         cudaFuncAttributeMaxDynamicSharedMemorySize, SMEM_BYTES);

    int total = 2048 + 2 * 2 * 5 * 16 * 64 * 4;
    prep_kernel<<<(total + 255) / 256, 256>>>(mu_w0, mu_w1, mu_w2, lv_w0, lv_w1, lv_w2);
    made_wave_kernel<<<2 * NB, 512, SMEM_BYTES>>>(x, mu_b0, mu_b1, mu_b2, mu_wo, mu_bo,
                                                  lv_b0, lv_b1, lv_b2, lv_wo, lv_bo, out);
}